// round 12
// baseline (speedup 1.0000x reference)
#include <cuda_runtime.h>
#include <cuda_fp16.h>
#include <cstdint>
#include <cstddef>

#define NSUP 65536
#define EDIM 512
#define CNUM 64
#define HNUM 8
#define LNUM 3
#define LN_EPS 1e-5f

// ---------------- static device scratch ----------------
__device__ __half g_Xh[NSUP * EDIM];
__device__ __half g_h[NSUP * EDIM];
__device__ float  g_feat[NSUP * EDIM];
__device__ __half g_W1t[LNUM * EDIM * EDIM];
__device__ __half g_W2t[LNUM * EDIM * EDIM];
__device__ float  g_WkT[EDIM * EDIM];
__device__ int    g_idx[NSUP];
__device__ int    g_cnti[CNUM];
__device__ int    g_off[CNUM + 1];
__device__ float  g_cnt[CNUM];
__device__ float  g_ctxp[CNUM * 8 * EDIM];
__device__ float  g_ctx[CNUM * EDIM];
__device__ float  g_q[CNUM * EDIM];
__device__ float  g_u[CNUM * HNUM * EDIM];
__device__ float  g_s[NSUP * HNUM];
__device__ float  g_attn[NSUP * HNUM];
__device__ float  g_mx[CNUM * HNUM];
__device__ float  g_sz[CNUM * HNUM];
__device__ float  g_wsp[CNUM * 8 * HNUM * EDIM];
__device__ float  g_ws[CNUM * HNUM * EDIM];
__device__ float  g_out[CNUM * EDIM];
__device__ float  g_coef[LNUM];

// ---------------- prep ----------------
__global__ void k_prep(const float* __restrict__ lw, const float* __restrict__ lt) {
    int tid = threadIdx.x;
    if (tid < CNUM) g_cnti[tid] = 0;
    if (tid == 0) {
        float m = fmaxf(lw[0], fmaxf(lw[1], lw[2]));
        float e0 = expf(lw[0] - m), e1 = expf(lw[1] - m), e2 = expf(lw[2] - m);
        float s = e0 + e1 + e2;
        g_coef[0] = e0 / s / lt[0];
        g_coef[1] = e1 / s / lt[1];
        g_coef[2] = e2 / s / lt[2];
    }
}

__global__ void k_convX(const float* __restrict__ X) {
    size_t i = ((size_t)blockIdx.x * 256 + threadIdx.x) * 8;
    float4 a = *(const float4*)(X + i);
    float4 b = *(const float4*)(X + i + 4);
    __half2* o = (__half2*)(g_Xh + i);
    o[0] = __floats2half2_rn(a.x, a.y);
    o[1] = __floats2half2_rn(a.z, a.w);
    o[2] = __floats2half2_rn(b.x, b.y);
    o[3] = __floats2half2_rn(b.z, b.w);
}

// z<3: W1[z]->g_W1t(fp16), z<6: W2[z-3]->g_W2t(fp16), z==6: Wk->g_WkT(fp32)
__global__ void k_transW(const float* __restrict__ W1, const float* __restrict__ W2,
                         const float* __restrict__ Wk) {
    __shared__ float t[32][33];
    int z = blockIdx.z;
    const float* src = (z < 3) ? (W1 + (size_t)z * EDIM * EDIM)
                     : (z < 6) ? (W2 + (size_t)(z - 3) * EDIM * EDIM)
                               : Wk;
    int x = blockIdx.x * 32 + threadIdx.x;
    int y = blockIdx.y * 32 + threadIdx.y;
    t[threadIdx.y][threadIdx.x] = src[(size_t)y * EDIM + x];
    __syncthreads();
    int orow = blockIdx.x * 32 + threadIdx.y;
    int ocol = blockIdx.y * 32 + threadIdx.x;
    float v = t[threadIdx.x][threadIdx.y];
    if (z < 3)      g_W1t[(size_t)z * EDIM * EDIM + (size_t)orow * EDIM + ocol] = __float2half_rn(v);
    else if (z < 6) g_W2t[(size_t)(z - 3) * EDIM * EDIM + (size_t)orow * EDIM + ocol] = __float2half_rn(v);
    else            g_WkT[(size_t)orow * EDIM + ocol] = v;
}

__global__ void k_hist(const int* __restrict__ labels) {
    __shared__ int hh[CNUM];
    int tid = threadIdx.x;
    if (tid < CNUM) hh[tid] = 0;
    __syncthreads();
    atomicAdd(&hh[labels[blockIdx.x * 256 + tid]], 1);
    __syncthreads();
    if (tid < CNUM) atomicAdd(&g_cnti[tid], hh[tid]);
}

__global__ void k_scan() {
    if (threadIdx.x == 0) {
        int s = 0;
        for (int c = 0; c < CNUM; c++) {
            g_off[c] = s;
            g_cnt[c] = (float)g_cnti[c];
            s += g_cnti[c];
        }
        g_off[CNUM] = s;
    }
}

// deterministic in-order scatter: one block per class
__global__ void k_scatter(const int* __restrict__ labels) {
    __shared__ int wsum[8];
    __shared__ int wbase[9];
    int c = blockIdx.x;
    int tid = threadIdx.x, lane = tid & 31, wid = tid >> 5;
    int base = g_off[c];
    for (int t0 = 0; t0 < NSUP; t0 += 256) {
        int i = t0 + tid;
        int flag = (labels[i] == c);
        unsigned mask = __ballot_sync(0xffffffffu, flag);
        int rank = __popc(mask & ((1u << lane) - 1u));
        if (lane == 0) wsum[wid] = __popc(mask);
        __syncthreads();
        if (tid == 0) {
            int s = 0;
            for (int w = 0; w < 8; w++) { wbase[w] = s; s += wsum[w]; }
            wbase[8] = s;
        }
        __syncthreads();
        if (flag) g_idx[base + wbase[wid] + rank] = i;
        base += wbase[8];
        __syncthreads();
    }
}

// ---------------- GEMM: C = A(MxK fp16) * Bt(NxK fp16)^T + bias ----------------
#define BM 128
#define BN 128
#define BK 32
#define BKP 40

__device__ __forceinline__ void cp_async16(unsigned s, const void* g) {
    asm volatile("cp.async.cg.shared.global [%0], [%1], 16;\n" :: "r"(s), "l"(g));
}
__device__ __forceinline__ void cp_commit() { asm volatile("cp.async.commit_group;\n"); }
template <int W> __device__ __forceinline__ void cp_wait() {
    asm volatile("cp.async.wait_group %0;\n" :: "n"(W));
}
__device__ __forceinline__ void mma16816(float* c, const uint32_t* a, const uint32_t* b) {
    asm volatile(
        "mma.sync.aligned.m16n8k16.row.col.f32.f16.f16.f32 "
        "{%0,%1,%2,%3}, {%4,%5,%6,%7}, {%8,%9}, {%0,%1,%2,%3};\n"
        : "+f"(c[0]), "+f"(c[1]), "+f"(c[2]), "+f"(c[3])
        : "r"(a[0]), "r"(a[1]), "r"(a[2]), "r"(a[3]), "r"(b[0]), "r"(b[1]));
}

__global__ void __launch_bounds__(256) k_gemm(int which, int lvl, const float* __restrict__ bias) {
    const __half* __restrict__ A  = which ? g_h : g_Xh;
    const __half* __restrict__ Bt = (which ? g_W2t : g_W1t) + (size_t)lvl * EDIM * EDIM;
    float* __restrict__ C = g_feat;

    __shared__ alignas(16) __half As[2][BM * BKP];
    __shared__ alignas(16) __half Bs[2][BN * BKP];

    int tid = threadIdx.x;
    int bm = blockIdx.x, bn = blockIdx.y;
    int lane = tid & 31, warp = tid >> 5;
    int wm = warp >> 2, wn = warp & 3;   // 2x4 warps, each 64x32 output
    int g = lane >> 2, tg = lane & 3;

    const __half* gA = A + (size_t)bm * BM * EDIM;
    const __half* gB = Bt + (size_t)bn * BN * EDIM;

    unsigned sA0 = (unsigned)__cvta_generic_to_shared(&As[0][0]);
    unsigned sA1 = (unsigned)__cvta_generic_to_shared(&As[1][0]);
    unsigned sB0 = (unsigned)__cvta_generic_to_shared(&Bs[0][0]);
    unsigned sB1 = (unsigned)__cvta_generic_to_shared(&Bs[1][0]);

    float acc[4][4][4];
    #pragma unroll
    for (int mi = 0; mi < 4; mi++)
        #pragma unroll
        for (int ni = 0; ni < 4; ni++) {
            acc[mi][ni][0] = 0.f; acc[mi][ni][1] = 0.f;
            acc[mi][ni][2] = 0.f; acc[mi][ni][3] = 0.f;
        }

    int r0 = tid >> 2, c0 = tid & 3;
    int r1 = r0 + 64;

    #define ISSUE(kt, buf) do {                                                              \
        unsigned sa_ = (buf) ? sA1 : sA0;                                                    \
        unsigned sb_ = (buf) ? sB1 : sB0;                                                    \
        cp_async16(sa_ + (unsigned)(r0 * BKP + c0 * 8) * 2,                                  \
                   gA + (size_t)r0 * EDIM + (kt) * BK + c0 * 8);                             \
        cp_async16(sb_ + (unsigned)(r0 * BKP + c0 * 8) * 2,                                  \
                   gB + (size_t)r0 * EDIM + (kt) * BK + c0 * 8);                             \
        cp_async16(sa_ + (unsigned)(r1 * BKP + c0 * 8) * 2,                                  \
                   gA + (size_t)r1 * EDIM + (kt) * BK + c0 * 8);                             \
        cp_async16(sb_ + (unsigned)(r1 * BKP + c0 * 8) * 2,                                  \
                   gB + (size_t)r1 * EDIM + (kt) * BK + c0 * 8);                             \
        cp_commit();                                                                         \
    } while (0)

    ISSUE(0, 0);
    const int KT = EDIM / BK;  // 16
    for (int kt = 0; kt < KT; kt++) {
        int cur = kt & 1;
        if (kt + 1 < KT) { ISSUE(kt + 1, cur ^ 1); cp_wait<1>(); }
        else             { cp_wait<0>(); }
        __syncthreads();

        const __half* pa = &As[cur][0];
        const __half* pb = &Bs[cur][0];
        #pragma unroll
        for (int ks = 0; ks < 2; ks++) {
            const int k0 = ks * 16;
            uint32_t af[4][4], bf[4][2];
            #pragma unroll
            for (int mi = 0; mi < 4; mi++) {
                int r = wm * 64 + mi * 16 + g;
                af[mi][0] = *(const uint32_t*)(pa + r * BKP + k0 + tg * 2);
                af[mi][1] = *(const uint32_t*)(pa + (r + 8) * BKP + k0 + tg * 2);
                af[mi][2] = *(const uint32_t*)(pa + r * BKP + k0 + tg * 2 + 8);
                af[mi][3] = *(const uint32_t*)(pa + (r + 8) * BKP + k0 + tg * 2 + 8);
            }
            #pragma unroll
            for (int ni = 0; ni < 4; ni++) {
                int n0 = wn * 32 + ni * 8 + g;
                bf[ni][0] = *(const uint32_t*)(pb + n0 * BKP + k0 + tg * 2);
                bf[ni][1] = *(const uint32_t*)(pb + n0 * BKP + k0 + tg * 2 + 8);
            }
            #pragma unroll
            for (int mi = 0; mi < 4; mi++)
                #pragma unroll
                for (int ni = 0; ni < 4; ni++)
                    mma16816(acc[mi][ni], af[mi], bf[ni]);
        }
        __syncthreads();
    }

    int rowB = bm * BM + wm * 64;
    int colB = bn * BN + wn * 32;
    #pragma unroll
    for (int mi = 0; mi < 4; mi++) {
        #pragma unroll
        for (int ni = 0; ni < 4; ni++) {
            int r = rowB + mi * 16 + g;
            int col = colB + ni * 8 + tg * 2;
            float b0 = bias[col], b1 = bias[col + 1];
            C[(size_t)r * EDIM + col]           = acc[mi][ni][0] + b0;
            C[(size_t)r * EDIM + col + 1]       = acc[mi][ni][1] + b1;
            C[(size_t)(r + 8) * EDIM + col]     = acc[mi][ni][2] + b0;
            C[(size_t)(r + 8) * EDIM + col + 1] = acc[mi][ni][3] + b1;
        }
    }
    #undef ISSUE
}

// ---------------- LayerNorm + ReLU -> fp16 (warp per row) ----------------
__global__ void k_lnrelu(const float* __restrict__ gamma, const float* __restrict__ beta) {
    int warp = threadIdx.x >> 5, lane = threadIdx.x & 31;
    size_t row = (size_t)blockIdx.x * 8 + warp;
    const float* x = g_feat + row * EDIM + lane * 16;
    float v[16];
    float s = 0.f, sq = 0.f;
    #pragma unroll
    for (int j = 0; j < 4; j++) {
        float4 f = *(const float4*)(x + j * 4);
        v[j*4+0] = f.x; v[j*4+1] = f.y; v[j*4+2] = f.z; v[j*4+3] = f.w;
        s += f.x + f.y + f.z + f.w;
        sq += f.x*f.x + f.y*f.y + f.z*f.z + f.w*f.w;
    }
    #pragma unroll
    for (int o = 16; o > 0; o >>= 1) {
        s  += __shfl_xor_sync(0xffffffffu, s, o);
        sq += __shfl_xor_sync(0xffffffffu, sq, o);
    }
    float mu = s * (1.f / EDIM);
    float var = sq * (1.f / EDIM) - mu * mu;
    float rs = rsqrtf(var + LN_EPS);
    const float* ga = gamma + lane * 16;
    const float* be = beta + lane * 16;
    __half2* o2 = (__half2*)(g_h + row * EDIM + lane * 16);
    #pragma unroll
    for (int j = 0; j < 8; j++) {
        float y0 = fmaxf((v[2*j]   - mu) * rs * ga[2*j]   + be[2*j],   0.f);
        float y1 = fmaxf((v[2*j+1] - mu) * rs * ga[2*j+1] + be[2*j+1], 0.f);
        o2[j] = __floats2half2_rn(y0, y1);
    }
}

// ---------------- class context (segment mean), deterministic 8-way ----------------
__global__ void k_ctxp() {
    int c = blockIdx.x, j = blockIdx.y, tid = threadIdx.x;
    int start = g_off[c], len = g_off[c + 1] - start;
    int ms = start + (len * j) / 8;
    int me = start + (len * (j + 1)) / 8;
    float a0 = 0.f, a1 = 0.f;
    for (int m = ms; m < me; m++) {
        int idx = g_idx[m];
        float2 f = *(const float2*)(g_feat + (size_t)idx * EDIM + 2 * tid);
        a0 += f.x; a1 += f.y;
    }
    g_ctxp[(size_t)(c * 8 + j) * EDIM + 2 * tid]     = a0;
    g_ctxp[(size_t)(c * 8 + j) * EDIM + 2 * tid + 1] = a1;
}

__global__ void k_ctxred() {
    int c = blockIdx.x, e = threadIdx.x;
    float s = 0.f;
    #pragma unroll
    for (int j = 0; j < 8; j++) s += g_ctxp[(size_t)(c * 8 + j) * EDIM + e];
    g_ctx[c * EDIM + e] = s / g_cnt[c];
}

// ---------------- q = ctx@Wq + bq ----------------
__global__ void k_q(const float* __restrict__ Wq, const float* __restrict__ bq) {
    __shared__ float cs[EDIM];
    int c = blockIdx.x, e = threadIdx.x;
    cs[e] = g_ctx[c * EDIM + e];
    __syncthreads();
    float acc = 0.f;
    for (int k = 0; k < EDIM; k++) acc += cs[k] * Wq[(size_t)k * EDIM + e];
    g_q[c * EDIM + e] = acc + bq[e];
}

// ---------------- u[c,h,e] = sum_d q[c,h,d] * Wk[e, h*64+d] ----------------
__global__ void k_u() {
    __shared__ float qs[64];
    int c = blockIdx.x, h = blockIdx.y, e = threadIdx.x;
    if (e < 64) qs[e] = g_q[c * EDIM + h * 64 + e];
    __syncthreads();
    float acc = 0.f;
    #pragma unroll 8
    for (int d = 0; d < 64; d++) acc += qs[d] * g_WkT[(size_t)(h * 64 + d) * EDIM + e];
    g_u[(size_t)(c * HNUM + h) * EDIM + e] = acc;
}

// ---------------- scores s[n,h] = scale * feat[n] . u[label[n],h] ----------------
__global__ void k_score(const int* __restrict__ labels) {
    int i = blockIdx.x * 256 + threadIdx.x;
    int n = i >> 3, h = i & 7;
    int lab = labels[n];
    const float4* f4 = (const float4*)(g_feat + (size_t)n * EDIM);
    const float4* u4 = (const float4*)(g_u + (size_t)(lab * HNUM + h) * EDIM);
    float acc = 0.f;
    #pragma unroll 4
    for (int k = 0; k < EDIM / 4; k++) {
        float4 f = f4[k], u = u4[k];
        acc += f.x * u.x + f.y * u.y + f.z * u.z + f.w * u.w;
    }
    g_s[i] = acc * 0.125f;  // 1/sqrt(64)
}

// ---------------- per (c,h): max & sumexp over members ----------------
__global__ void k_smax() {
    __shared__ float red[256];
    int b = blockIdx.x, c = b >> 3, h = b & 7, tid = threadIdx.x;
    int s0 = g_off[c], s1 = g_off[c + 1];
    float m = -1e30f;
    for (int i = s0 + tid; i < s1; i += 256) m = fmaxf(m, g_s[g_idx[i] * HNUM + h]);
    red[tid] = m;
    __syncthreads();
    #pragma unroll
    for (int o = 128; o > 0; o >>= 1) {
        if (tid < o) red[tid] = fmaxf(red[tid], red[tid + o]);
        __syncthreads();
    }
    float mx = red[0];
    __syncthreads();
    float sum = 0.f;
    for (int i = s0 + tid; i < s1; i += 256) sum += expf(g_s[g_idx[i] * HNUM + h] - mx);
    red[tid] = sum;
    __syncthreads();
    #pragma unroll
    for (int o = 128; o > 0; o >>= 1) {
        if (tid < o) red[tid] += red[tid + o];
        __syncthreads();
    }
    if (tid == 0) { g_mx[b] = mx; g_sz[b] = red[0]; }
}

__global__ void k_attn(const int* __restrict__ labels) {
    int i = blockIdx.x * 256 + threadIdx.x;
    int n = i >> 3, h = i & 7;
    int b = labels[n] * HNUM + h;
    g_attn[i] = expf(g_s[i] - g_mx[b]) / g_sz[b];
}

// ---------------- ws[c,h,e] = sum_{n in c} attn[n,h]*feat[n,e] ----------------
__global__ void k_wsump() {
    __shared__ float as[HNUM];
    int c = blockIdx.x, j = blockIdx.y, tid = threadIdx.x;
    int start = g_off[c], len = g_off[c + 1] - start;
    int ms = start + (len * j) / 8;
    int me = start + (len * (j + 1)) / 8;
    float acc[HNUM][2];
    #pragma unroll
    for (int h = 0; h < HNUM; h++) { acc[h][0] = 0.f; acc[h][1] = 0.f; }
    for (int m = ms; m < me; m++) {
        int idx = g_idx[m];
        if (tid < HNUM) as[tid] = g_attn[idx * HNUM + tid];
        __syncthreads();
        float2 f = *(const float2*)(g_feat + (size_t)idx * EDIM + 2 * tid);
        #pragma unroll
        for (int h = 0; h < HNUM; h++) {
            acc[h][0] += as[h] * f.x;
            acc[h][1] += as[h] * f.y;
        }
        __syncthreads();
    }
    #pragma unroll
    for (int h = 0; h < HNUM; h++) {
        size_t base = ((size_t)(c * 8 + j) * HNUM + h) * EDIM + 2 * tid;
        g_wsp[base]     = acc[h][0];
        g_wsp[base + 1] = acc[h][1];
    }
}

__global__ void k_wsred() {
    int b = blockIdx.x;        // c*8+h
    int c = b >> 3, h = b & 7, e = threadIdx.x;
    float s = 0.f;
    #pragma unroll
    for (int j = 0; j < 8; j++) s += g_wsp[((size_t)(c * 8 + j) * HNUM + h) * EDIM + e];
    g_ws[(size_t)b * EDIM + e] = s;
}

// ---------------- out[c,x] = ws[c, x/64, :] @ Wv[:, x] + bv[x] ----------------
__global__ void k_out(const float* __restrict__ Wv, const float* __restrict__ bv) {
    __shared__ float ws_s[HNUM * EDIM];
    int c = blockIdx.x, x = threadIdx.x;
    #pragma unroll
    for (int j = 0; j < 8; j++) ws_s[j * EDIM + x] = g_ws[(size_t)(c * HNUM) * EDIM + j * EDIM + x];
    __syncthreads();
    int h = x >> 6;
    float acc = 0.f;
    for (int e = 0; e < EDIM; e++) acc += ws_s[h * EDIM + e] * Wv[(size_t)e * EDIM + x];
    g_out[c * EDIM + x] = acc + bv[x];
}

// ---------------- proto = out@Wo + bo; final accumulate ----------------
__global__ void k_proto(const float* __restrict__ Wo, const float* __restrict__ bo,
                        int lvl, float* __restrict__ fin) {
    __shared__ float os[EDIM];
    int c = blockIdx.x, e = threadIdx.x;
    os[e] = g_out[c * EDIM + e];
    __syncthreads();
    float acc = 0.f;
    for (int k = 0; k < EDIM; k++) acc += os[k] * Wo[(size_t)k * EDIM + e];
    float v = (acc + bo[e]) * g_coef[lvl];
    if (lvl == 0) fin[c * EDIM + e] = v;
    else          fin[c * EDIM + e] += v;
}

// ---------------- launch ----------------
extern "C" void kernel_launch(void* const* d_in, const int* in_sizes, int n_in,
                              void* d_out, int out_size) {
    const float* X      = (const float*)d_in[0];
    const int*   labels = (const int*)d_in[1];
    const float* W1     = (const float*)d_in[2];
    const float* b1     = (const float*)d_in[3];
    const float* gamma  = (const float*)d_in[4];
    const float* beta   = (const float*)d_in[5];
    const float* W2     = (const float*)d_in[6];
    const float* b2     = (const float*)d_in[7];
    const float* Wq     = (const float*)d_in[8];
    const float* bq     = (const float*)d_in[9];
    const float* Wk     = (const float*)d_in[10];
    // d_in[11]=bk cancels in softmax
    const float* Wv     = (const float*)d_in[12];
    const float* bv     = (const float*)d_in[13];
    const float* Wo     = (const float*)d_in[14];
    const float* bo     = (const float*)d_in[15];
    const float* lw     = (const float*)d_in[16];
    const float* lt     = (const float*)d_in[17];
    float* fin = (float*)d_out;

    k_prep<<<1, 64>>>(lw, lt);
    k_convX<<<(NSUP * EDIM / 8) / 256, 256>>>(X);
    k_transW<<<dim3(16, 16, 7), dim3(32, 32)>>>(W1, W2, Wk);
    k_hist<<<NSUP / 256, 256>>>(labels);
    k_scan<<<1, 32>>>();
    k_scatter<<<CNUM, 256>>>(labels);

    for (int l = 0; l < LNUM; l++) {
        k_gemm<<<dim3(NSUP / BM, EDIM / BN), 256>>>(0, l, b1 + l * EDIM);
        k_lnrelu<<<NSUP / 8, 256>>>(gamma + l * EDIM, beta + l * EDIM);
        k_gemm<<<dim3(NSUP / BM, EDIM / BN), 256>>>(1, l, b2 + l * EDIM);
        k_ctxp<<<dim3(CNUM, 8), 256>>>();
        k_ctxred<<<CNUM, EDIM>>>();
        k_q<<<CNUM, EDIM>>>(Wq, bq);
        k_u<<<dim3(CNUM, HNUM), EDIM>>>();
        k_score<<<NSUP * HNUM / 256, 256>>>(labels);
        k_smax<<<CNUM * HNUM, 256>>>();
        k_attn<<<NSUP * HNUM / 256, 256>>>(labels);
        k_wsump<<<dim3(CNUM, 8), 256>>>();
        k_wsred<<<CNUM * HNUM, EDIM>>>();
        k_out<<<CNUM, EDIM>>>(Wv, bv);
        k_proto<<<CNUM, EDIM>>>(Wo, bo, l, fin);
    }
}

// round 15
// speedup vs baseline: 1.1580x; 1.1580x over previous
#include <cuda_runtime.h>
#include <cuda_fp16.h>
#include <cstdint>
#include <cstddef>

#define NSUP 65536
#define EDIM 512
#define CNUM 64
#define HNUM 8
#define LNUM 3
#define LN_EPS 1e-5f

// ---------------- static device scratch ----------------
__device__ __half g_Xh[NSUP * EDIM];
__device__ __half g_h[NSUP * EDIM];
__device__ float  g_feat[NSUP * EDIM];
__device__ __half g_W1t[LNUM * EDIM * EDIM];
__device__ __half g_W2t[LNUM * EDIM * EDIM];
__device__ float  g_WkT[EDIM * EDIM];
__device__ int    g_idx[NSUP];
__device__ int    g_cnti[CNUM];
__device__ int    g_off[CNUM + 1];
__device__ float  g_cnt[CNUM];
__device__ float  g_ctxp[CNUM * 8 * EDIM];
__device__ float  g_ctx[CNUM * EDIM];
__device__ float  g_q[CNUM * EDIM];
__device__ float  g_u[CNUM * HNUM * EDIM];
__device__ float  g_s[NSUP * HNUM];
__device__ float  g_attn[NSUP * HNUM];
__device__ float  g_mx[CNUM * HNUM];
__device__ float  g_sz[CNUM * HNUM];
__device__ float  g_wsp[CNUM * 8 * HNUM * EDIM];
__device__ float  g_ws[CNUM * HNUM * EDIM];
__device__ float  g_out[CNUM * EDIM];
__device__ float  g_coef[LNUM];

// ---------------- prep ----------------
__global__ void k_prep(const float* __restrict__ lw, const float* __restrict__ lt) {
    int tid = threadIdx.x;
    if (tid < CNUM) g_cnti[tid] = 0;
    if (tid == 0) {
        float m = fmaxf(lw[0], fmaxf(lw[1], lw[2]));
        float e0 = expf(lw[0] - m), e1 = expf(lw[1] - m), e2 = expf(lw[2] - m);
        float s = e0 + e1 + e2;
        g_coef[0] = e0 / s / lt[0];
        g_coef[1] = e1 / s / lt[1];
        g_coef[2] = e2 / s / lt[2];
    }
}

__global__ void k_convX(const float* __restrict__ X) {
    size_t i = ((size_t)blockIdx.x * 256 + threadIdx.x) * 8;
    float4 a = *(const float4*)(X + i);
    float4 b = *(const float4*)(X + i + 4);
    __half2* o = (__half2*)(g_Xh + i);
    o[0] = __floats2half2_rn(a.x, a.y);
    o[1] = __floats2half2_rn(a.z, a.w);
    o[2] = __floats2half2_rn(b.x, b.y);
    o[3] = __floats2half2_rn(b.z, b.w);
}

// z<3: W1[z]->g_W1t(fp16), z<6: W2[z-3]->g_W2t(fp16), z==6: Wk->g_WkT(fp32)
__global__ void k_transW(const float* __restrict__ W1, const float* __restrict__ W2,
                         const float* __restrict__ Wk) {
    __shared__ float t[32][33];
    int z = blockIdx.z;
    const float* src = (z < 3) ? (W1 + (size_t)z * EDIM * EDIM)
                     : (z < 6) ? (W2 + (size_t)(z - 3) * EDIM * EDIM)
                               : Wk;
    int x = blockIdx.x * 32 + threadIdx.x;
    int y = blockIdx.y * 32 + threadIdx.y;
    t[threadIdx.y][threadIdx.x] = src[(size_t)y * EDIM + x];
    __syncthreads();
    int orow = blockIdx.x * 32 + threadIdx.y;
    int ocol = blockIdx.y * 32 + threadIdx.x;
    float v = t[threadIdx.x][threadIdx.y];
    if (z < 3)      g_W1t[(size_t)z * EDIM * EDIM + (size_t)orow * EDIM + ocol] = __float2half_rn(v);
    else if (z < 6) g_W2t[(size_t)(z - 3) * EDIM * EDIM + (size_t)orow * EDIM + ocol] = __float2half_rn(v);
    else            g_WkT[(size_t)orow * EDIM + ocol] = v;
}

__global__ void k_hist(const int* __restrict__ labels) {
    __shared__ int hh[CNUM];
    int tid = threadIdx.x;
    if (tid < CNUM) hh[tid] = 0;
    __syncthreads();
    atomicAdd(&hh[labels[blockIdx.x * 256 + tid]], 1);
    __syncthreads();
    if (tid < CNUM) atomicAdd(&g_cnti[tid], hh[tid]);
}

__global__ void k_scan() {
    if (threadIdx.x == 0) {
        int s = 0;
        for (int c = 0; c < CNUM; c++) {
            g_off[c] = s;
            g_cnt[c] = (float)g_cnti[c];
            s += g_cnti[c];
        }
        g_off[CNUM] = s;
    }
}

// deterministic in-order scatter: one block per class
__global__ void k_scatter(const int* __restrict__ labels) {
    __shared__ int wsum[8];
    __shared__ int wbase[9];
    int c = blockIdx.x;
    int tid = threadIdx.x, lane = tid & 31, wid = tid >> 5;
    int base = g_off[c];
    for (int t0 = 0; t0 < NSUP; t0 += 256) {
        int i = t0 + tid;
        int flag = (labels[i] == c);
        unsigned mask = __ballot_sync(0xffffffffu, flag);
        int rank = __popc(mask & ((1u << lane) - 1u));
        if (lane == 0) wsum[wid] = __popc(mask);
        __syncthreads();
        if (tid == 0) {
            int s = 0;
            for (int w = 0; w < 8; w++) { wbase[w] = s; s += wsum[w]; }
            wbase[8] = s;
        }
        __syncthreads();
        if (flag) g_idx[base + wbase[wid] + rank] = i;
        base += wbase[8];
        __syncthreads();
    }
}

// ================= GEMM: C = A(MxK fp16) * Bt(NxK fp16)^T + bias =================
// Grid (NSUP/128, EDIM/256), 256 threads, dynamic smem GEMM_SMEM — identical for
// both device-side implementations (tcgen05 on arch-specific pass, mma.sync else).
#define TBM 128
#define TBN 256
#define TBK 64
#define NCH (EDIM / TBK)   // 8

#define SM_TPTR 0
#define SM_MB   8
#define SM_A    1024
#define A_ST    (TBM * TBK * 2)            // 16384
#define SM_B    (SM_A + 2 * A_ST)          // 33792
#define B_ST    (TBN * TBK * 2)            // 32768
#define GEMM_SMEM (SM_B + 2 * B_ST)        // 99328

// SW128 K-major descriptor base: layout=SW128(2), version=1, SBO=64, LBO=1
#define DESC_BASE ((2ull << 61) | (1ull << 46) | (64ull << 32) | (1ull << 16))
// idesc: dtype=F32, atype=btype=F16(0), N=256, M=128 (cg1)
#define GEMM_IDESC ((1u << 4) | ((TBN / 8) << 17) | ((TBM / 16) << 24))

#if defined(__CUDA_ARCH_FEAT_SM103_ALL) || defined(__CUDA_ARCH_FEAT_SM100_ALL) || \
    (defined(__CUDA_ARCH_SPECIFIC__) && (__CUDA_ARCH_SPECIFIC__ >= 1000))
#define USE_TCGEN05 1
#else
#define USE_TCGEN05 0
#endif

__device__ __forceinline__ uint32_t sm_u32(const void* p) {
    uint32_t a;
    asm("{ .reg .u64 t; cvta.to.shared.u64 t, %1; cvt.u32.u64 %0, t; }" : "=r"(a) : "l"(p));
    return a;
}
__device__ __forceinline__ void cp_async16(unsigned s, const void* g) {
    asm volatile("cp.async.cg.shared.global [%0], [%1], 16;\n" :: "r"(s), "l"(g));
}
__device__ __forceinline__ void cp_commit() { asm volatile("cp.async.commit_group;\n"); }
template <int W> __device__ __forceinline__ void cp_wait() {
    asm volatile("cp.async.wait_group %0;\n" :: "n"(W));
}

#if USE_TCGEN05
__device__ __forceinline__ uint32_t elect1() {
    uint32_t p;
    asm volatile("{ .reg .pred p; elect.sync _|p, 0xFFFFFFFF; selp.b32 %0, 1, 0, p; }" : "=r"(p));
    return p;
}
__device__ __forceinline__ void mwait(uint32_t addr, uint32_t par) {
    asm volatile(
        "{\n\t.reg .pred P;\n\t"
        "LW%=:\n\t"
        "mbarrier.try_wait.parity.shared.b64 P, [%0], %1;\n\t"
        "@P bra LD%=;\n\t"
        "bra LW%=;\n\t"
        "LD%=:\n\t}"
        :: "r"(addr), "r"(par) : "memory");
}
__device__ __forceinline__ void mma_f16_ss(uint32_t d, uint64_t ad, uint64_t bd,
                                           uint32_t idesc, uint32_t en) {
    asm volatile(
        "{\n\t.reg .pred p;\n\t"
        "setp.ne.u32 p, %4, 0;\n\t"
        "tcgen05.mma.cta_group::1.kind::f16 [%0], %1, %2, %3, {%5,%5,%5,%5}, p;\n\t}"
        :: "r"(d), "l"(ad), "l"(bd), "r"(idesc), "r"(en), "r"(0u) : "memory");
}
#else
__device__ __forceinline__ void mma16816(float* c, const uint32_t* a, const uint32_t* b) {
    asm volatile(
        "mma.sync.aligned.m16n8k16.row.col.f32.f16.f16.f32 "
        "{%0,%1,%2,%3}, {%4,%5,%6,%7}, {%8,%9}, {%0,%1,%2,%3};\n"
        : "+f"(c[0]), "+f"(c[1]), "+f"(c[2]), "+f"(c[3])
        : "r"(a[0]), "r"(a[1]), "r"(a[2]), "r"(a[3]), "r"(b[0]), "r"(b[1]));
}
#endif

__global__ void __launch_bounds__(256) k_gemm5(const __half* __restrict__ A,
                                               const __half* __restrict__ Bt,
                                               const float* __restrict__ bias,
                                               float* __restrict__ C) {
#if USE_TCGEN05
    extern __shared__ char smem[];
    uint32_t sb = sm_u32(smem);
    int tid = threadIdx.x, lane = tid & 31, warp = tid >> 5;
    int bm = blockIdx.x, bn = blockIdx.y;

    if (warp == 0) {
        asm volatile("tcgen05.alloc.cta_group::1.sync.aligned.shared::cta.b32 [%0], %1;"
                     :: "r"(sb + SM_TPTR), "r"(256) : "memory");
        asm volatile("tcgen05.relinquish_alloc_permit.cta_group::1.sync.aligned;");
    }
    if (tid == 0) {
        asm volatile("mbarrier.init.shared.b64 [%0], 1;" :: "r"(sb + SM_MB) : "memory");
        asm volatile("mbarrier.init.shared.b64 [%0], 1;" :: "r"(sb + SM_MB + 8) : "memory");
    }
    __syncthreads();
    uint32_t tmem;
    asm volatile("ld.shared.b32 %0, [%1];" : "=r"(tmem) : "r"(sb + SM_TPTR));

    const __half* gA = A + (size_t)bm * TBM * EDIM;
    const __half* gB = Bt + (size_t)bn * TBN * EDIM;

    // SW128-swizzled cp.async loads; 16B unit at row*128 + uc*16, swizzled
    #define LOAD_A(ch, st) do {                                                       \
        unsigned base_ = sb + SM_A + (st) * A_ST;                                     \
        _Pragma("unroll")                                                             \
        for (int j_ = 0; j_ < 4; j_++) {                                              \
            int u_ = tid + j_ * 256;                                                  \
            int row_ = u_ >> 3, uc_ = u_ & 7;                                         \
            uint32_t off_ = (uint32_t)(row_ * 128 + uc_ * 16);                        \
            uint32_t sw_ = off_ ^ ((off_ >> 3) & 0x70);                               \
            cp_async16(base_ + sw_, gA + (size_t)row_ * EDIM + (ch) * TBK + uc_ * 8); \
        }                                                                             \
    } while (0)
    #define LOAD_B(ch, st) do {                                                       \
        unsigned base_ = sb + SM_B + (st) * B_ST;                                     \
        _Pragma("unroll")                                                             \
        for (int j_ = 0; j_ < 8; j_++) {                                              \
            int u_ = tid + j_ * 256;                                                  \
            int row_ = u_ >> 3, uc_ = u_ & 7;                                         \
            uint32_t off_ = (uint32_t)(row_ * 128 + uc_ * 16);                        \
            uint32_t sw_ = off_ ^ ((off_ >> 3) & 0x70);                               \
            cp_async16(base_ + sw_, gB + (size_t)row_ * EDIM + (ch) * TBK + uc_ * 8); \
        }                                                                             \
    } while (0)

    LOAD_A(0, 0); LOAD_B(0, 0); cp_commit();
    LOAD_A(1, 1); LOAD_B(1, 1); cp_commit();

    for (int i = 0; i < NCH; i++) {
        int st = i & 1;
        if (i < NCH - 1) cp_wait<1>(); else cp_wait<0>();
        __syncthreads();
        if (warp == 0) {
            asm volatile("fence.proxy.async.shared::cta;" ::: "memory");
            if (elect1()) {
                uint64_t ad = DESC_BASE | (uint64_t)(((sb + SM_A + st * A_ST) >> 4) & 0x3FFF);
                uint64_t bd = DESC_BASE | (uint64_t)(((sb + SM_B + st * B_ST) >> 4) & 0x3FFF);
                #pragma unroll
                for (int s = 0; s < 4; s++)
                    mma_f16_ss(tmem, ad + 2 * s, bd + 2 * s, GEMM_IDESC,
                               (i > 0 || s > 0) ? 1u : 0u);
                asm volatile(
                    "tcgen05.commit.cta_group::1.mbarrier::arrive::one.shared::cluster.b64 [%0];"
                    :: "r"(sb + SM_MB + st * 8) : "memory");
            }
        }
        if (i + 2 < NCH) {
            mwait(sb + SM_MB + st * 8, (uint32_t)((i >> 1) & 1));
            LOAD_A(i + 2, st); LOAD_B(i + 2, st); cp_commit();
        }
    }
    // last commit on mbar[1] was its 4th arrival -> wait parity 1 (covers all mmas)
    mwait(sb + SM_MB + 8, 1u);
    asm volatile("tcgen05.fence::after_thread_sync;" ::: "memory");

    // epilogue: wg0 (warps 0-3) cols 0..127, wg1 (warps 4-7) cols 128..255;
    // warp w reads its own subpartition (w&3), lane field = (w&3)*32 << 16
    int wg = warp >> 2, sub = warp & 3;
    int row = bm * TBM + sub * 32 + lane;
    #pragma unroll
    for (int j = 0; j < 4; j++) {
        uint32_t r[32];
        uint32_t taddr = tmem + ((uint32_t)sub << 21) + (uint32_t)(wg * 128 + j * 32);
        asm volatile(
            "tcgen05.ld.sync.aligned.32x32b.x32.b32 "
            "{%0, %1, %2, %3, %4, %5, %6, %7, "
            " %8, %9, %10, %11, %12, %13, %14, %15, "
            " %16, %17, %18, %19, %20, %21, %22, %23, "
            " %24, %25, %26, %27, %28, %29, %30, %31}, [%32];"
            : "=r"(r[0]),  "=r"(r[1]),  "=r"(r[2]),  "=r"(r[3]),
              "=r"(r[4]),  "=r"(r[5]),  "=r"(r[6]),  "=r"(r[7]),
              "=r"(r[8]),  "=r"(r[9]),  "=r"(r[10]), "=r"(r[11]),
              "=r"(r[12]), "=r"(r[13]), "=r"(r[14]), "=r"(r[15]),
              "=r"(r[16]), "=r"(r[17]), "=r"(r[18]), "=r"(r[19]),
              "=r"(r[20]), "=r"(r[21]), "=r"(r[22]), "=r"(r[23]),
              "=r"(r[24]), "=r"(r[25]), "=r"(r[26]), "=r"(r[27]),
              "=r"(r[28]), "=r"(r[29]), "=r"(r[30]), "=r"(r[31])
            : "r"(taddr));
        asm volatile("tcgen05.wait::ld.sync.aligned;" ::: "memory");
        int colb = bn * TBN + wg * 128 + j * 32;
        float* crow = C + (size_t)row * EDIM + colb;
        #pragma unroll
        for (int k = 0; k < 8; k++) {
            float4 o;
            o.x = __uint_as_float(r[k * 4 + 0]) + bias[colb + k * 4 + 0];
            o.y = __uint_as_float(r[k * 4 + 1]) + bias[colb + k * 4 + 1];
            o.z = __uint_as_float(r[k * 4 + 2]) + bias[colb + k * 4 + 2];
            o.w = __uint_as_float(r[k * 4 + 3]) + bias[colb + k * 4 + 3];
            *(float4*)(crow + k * 4) = o;
        }
    }

    __syncthreads();
    if (warp == 0)
        asm volatile("tcgen05.dealloc.cta_group::1.sync.aligned.b32 %0, %1;"
                     :: "r"(tmem), "r"(256));
    #undef LOAD_A
    #undef LOAD_B
#else
    // ---------- fallback: mma.sync (validated R12), two 128-col halves ----------
    extern __shared__ char smem[];
    __half* Asm = (__half*)smem;                              // [2][128*40]
    __half* Bsm = (__half*)(smem + 2 * 128 * 40 * 2);         // [2][128*40]
    unsigned sA = sm_u32(Asm), sB = sm_u32(Bsm);
    const unsigned STB = 128 * 40 * 2;                        // stage bytes

    int tid = threadIdx.x, lane = tid & 31, warp = tid >> 5;
    int bm = blockIdx.x;
    int wm = warp >> 2, wn = warp & 3;
    int g = lane >> 2, tg = lane & 3;
    const __half* gA = A + (size_t)bm * 128 * EDIM;
    int r0 = tid >> 2, c0 = tid & 3;
    int r1 = r0 + 64;

    for (int nh = 0; nh < 2; nh++) {
        const __half* gB = Bt + (size_t)(blockIdx.y * 2 + nh) * 128 * EDIM;
        __syncthreads();

        float acc[4][4][4];
        #pragma unroll
        for (int mi = 0; mi < 4; mi++)
            #pragma unroll
            for (int ni = 0; ni < 4; ni++) {
                acc[mi][ni][0] = 0.f; acc[mi][ni][1] = 0.f;
                acc[mi][ni][2] = 0.f; acc[mi][ni][3] = 0.f;
            }

        #define FISSUE(kt, buf) do {                                                     \
            unsigned o_ = (buf) * STB;                                                   \
            cp_async16(sA + o_ + (unsigned)(r0 * 40 + c0 * 8) * 2,                       \
                       gA + (size_t)r0 * EDIM + (kt) * 32 + c0 * 8);                     \
            cp_async16(sB + o_ + (unsigned)(r0 * 40 + c0 * 8) * 2,                       \
                       gB + (size_t)r0 * EDIM + (kt) * 32 + c0 * 8);                     \
            cp_async16(sA + o_ + (unsigned)(r1 * 40 + c0 * 8) * 2,                       \
                       gA + (size_t)r1 * EDIM + (kt) * 32 + c0 * 8);                     \
            cp_async16(sB + o_ + (unsigned)(r1 * 40 + c0 * 8) * 2,                       \
                       gB + (size_t)r1 * EDIM + (kt) * 32 + c0 * 8);                     \
            cp_commit();                                                                 \
        } while (0)

        FISSUE(0, 0);
        const int KT = EDIM / 32;  // 16
        for (int kt = 0; kt < KT; kt++) {
            int cur = kt & 1;
            if (kt + 1 < KT) { FISSUE(kt + 1, cur ^ 1); cp_wait<1>(); }
            else             { cp_wait<0>(); }
            __syncthreads();

            const __half* pa = Asm + cur * 128 * 40;
            const __half* pb = Bsm + cur * 128 * 40;
            #pragma unroll
            for (int ks = 0; ks < 2; ks++) {
                const int k0 = ks * 16;
                uint32_t af[4][4], bf[4][2];
                #pragma unroll
                for (int mi = 0; mi < 4; mi++) {
                    int r = wm * 64 + mi * 16 + g;
                    af[mi][0] = *(const uint32_t*)(pa + r * 40 + k0 + tg * 2);
                    af[mi][1] = *(const uint32_t*)(pa + (r + 8) * 40 + k0 + tg * 2);
                    af[mi][2] = *(const uint32_t*)(pa + r * 40 + k0 + tg * 2 + 8);
                    af[mi][3] = *(const uint32_t*)(pa + (r + 8) * 40 + k0 + tg * 2 + 8);
                }
                #pragma unroll
                for (int ni = 0; ni < 4; ni++) {
                    int n0 = wn * 32 + ni * 8 + g;
                    bf[ni][0] = *(const uint32_t*)(pb + n0 * 40 + k0 + tg * 2);
                    bf[ni][1] = *(const uint32_t*)(pb + n0 * 40 + k0 + tg * 2 + 8);
                }
                #pragma unroll
                for (int mi = 0; mi < 4; mi++)
                    #pragma unroll
                    for (int ni = 0; ni < 4; ni++)
                        mma16816(acc[mi][ni], af[mi], bf[ni]);
            }
            __syncthreads();
        }

        int rowB = bm * 128 + wm * 64;
        int colB = (blockIdx.y * 2 + nh) * 128 + wn * 32;
        #pragma unroll
        for (int mi = 0; mi < 4; mi++) {
            #pragma unroll
            for (int ni = 0; ni < 4; ni++) {
                int r = rowB + mi * 16 + g;
                int col = colB + ni * 8 + tg * 2;
                float b0 = bias[col], b1 = bias[col + 1];
                C[(size_t)r * EDIM + col]           = acc[mi][ni][0] + b0;
                C[(size_t)r * EDIM + col + 1]       = acc[mi][ni][1] + b1;
                C[(size_t)(r + 8) * EDIM + col]     = acc[mi][ni][2] + b0;
                C[(size_t)(r + 8) * EDIM + col + 1] = acc[mi][ni][3] + b1;
            }
        }
        #undef FISSUE
    }
#endif
}

// ---------------- LayerNorm + ReLU -> fp16 (warp per row) ----------------
__global__ void k_lnrelu(const float* __restrict__ gamma, const float* __restrict__ beta) {
    int warp = threadIdx.x >> 5, lane = threadIdx.x & 31;
    size_t row = (size_t)blockIdx.x * 8 + warp;
    const float* x = g_feat + row * EDIM + lane * 16;
    float v[16];
    float s = 0.f, sq = 0.f;
    #pragma unroll
    for (int j = 0; j < 4; j++) {
        float4 f = *(const float4*)(x + j * 4);
        v[j*4+0] = f.x; v[j*4+1] = f.y; v[j*4+2] = f.z; v[j*4+3] = f.w;
        s += f.x + f.y + f.z + f.w;
        sq += f.x*f.x + f.y*f.y + f.z*f.z + f.w*f.w;
    }
    #pragma unroll
    for (int o = 16; o > 0; o >>= 1) {
        s  += __shfl_xor_sync(0xffffffffu, s, o);
        sq += __shfl_xor_sync(0xffffffffu, sq, o);
    }
    float mu = s * (1.f / EDIM);
    float var = sq * (1.f / EDIM) - mu * mu;
    float rs = rsqrtf(var + LN_EPS);
    const float* ga = gamma + lane * 16;
    const float* be = beta + lane * 16;
    __half2* o2 = (__half2*)(g_h + row * EDIM + lane * 16);
    #pragma unroll
    for (int j = 0; j < 8; j++) {
        float y0 = fmaxf((v[2*j]   - mu) * rs * ga[2*j]   + be[2*j],   0.f);
        float y1 = fmaxf((v[2*j+1] - mu) * rs * ga[2*j+1] + be[2*j+1], 0.f);
        o2[j] = __floats2half2_rn(y0, y1);
    }
}

// ---------------- class context (segment mean), deterministic 8-way ----------------
__global__ void k_ctxp() {
    int c = blockIdx.x, j = blockIdx.y, tid = threadIdx.x;
    int start = g_off[c], len = g_off[c + 1] - start;
    int ms = start + (len * j) / 8;
    int me = start + (len * (j + 1)) / 8;
    float a0 = 0.f, a1 = 0.f;
    for (int m = ms; m < me; m++) {
        int idx = g_idx[m];
        float2 f = *(const float2*)(g_feat + (size_t)idx * EDIM + 2 * tid);
        a0 += f.x; a1 += f.y;
    }
    g_ctxp[(size_t)(c * 8 + j) * EDIM + 2 * tid]     = a0;
    g_ctxp[(size_t)(c * 8 + j) * EDIM + 2 * tid + 1] = a1;
}

__global__ void k_ctxred() {
    int c = blockIdx.x, e = threadIdx.x;
    float s = 0.f;
    #pragma unroll
    for (int j = 0; j < 8; j++) s += g_ctxp[(size_t)(c * 8 + j) * EDIM + e];
    g_ctx[c * EDIM + e] = s / g_cnt[c];
}

// ---------------- q = ctx@Wq + bq ----------------
__global__ void k_q(const float* __restrict__ Wq, const float* __restrict__ bq) {
    __shared__ float cs[EDIM];
    int c = blockIdx.x, e = threadIdx.x;
    cs[e] = g_ctx[c * EDIM + e];
    __syncthreads();
    float acc = 0.f;
    for (int k = 0; k < EDIM; k++) acc += cs[k] * Wq[(size_t)k * EDIM + e];
    g_q[c * EDIM + e] = acc + bq[e];
}

// ---------------- u[c,h,e] = sum_d q[c,h,d] * Wk[e, h*64+d] ----------------
__global__ void k_u() {
    __shared__ float qs[64];
    int c = blockIdx.x, h = blockIdx.y, e = threadIdx.x;
    if (e < 64) qs[e] = g_q[c * EDIM + h * 64 + e];
    __syncthreads();
    float acc = 0.f;
    #pragma unroll 8
    for (int d = 0; d < 64; d++) acc += qs[d] * g_WkT[(size_t)(h * 64 + d) * EDIM + e];
    g_u[(size_t)(c * HNUM + h) * EDIM + e] = acc;
}

// ---------------- scores s[n,h] = scale * feat[n] . u[label[n],h] ----------------
__global__ void k_score(const int* __restrict__ labels) {
    int i = blockIdx.x * 256 + threadIdx.x;
    int n = i >> 3, h = i & 7;
    int lab = labels[n];
    const float4* f4 = (const float4*)(g_feat + (size_t)n * EDIM);
    const float4* u4 = (const float4*)(g_u + (size_t)(lab * HNUM + h) * EDIM);
    float acc = 0.f;
    #pragma unroll 4
    for (int k = 0; k < EDIM / 4; k++) {
        float4 f = f4[k], u = u4[k];
        acc += f.x * u.x + f.y * u.y + f.z * u.z + f.w * u.w;
    }
    g_s[i] = acc * 0.125f;  // 1/sqrt(64)
}

// ---------------- per (c,h): max & sumexp over members ----------------
__global__ void k_smax() {
    __shared__ float red[256];
    int b = blockIdx.x, c = b >> 3, h = b & 7, tid = threadIdx.x;
    int s0 = g_off[c], s1 = g_off[c + 1];
    float m = -1e30f;
    for (int i = s0 + tid; i < s1; i += 256) m = fmaxf(m, g_s[g_idx[i] * HNUM + h]);
    red[tid] = m;
    __syncthreads();
    #pragma unroll
    for (int o = 128; o > 0; o >>= 1) {
        if (tid < o) red[tid] = fmaxf(red[tid], red[tid + o]);
        __syncthreads();
    }
    float mx = red[0];
    __syncthreads();
    float sum = 0.f;
    for (int i = s0 + tid; i < s1; i += 256) sum += expf(g_s[g_idx[i] * HNUM + h] - mx);
    red[tid] = sum;
    __syncthreads();
    #pragma unroll
    for (int o = 128; o > 0; o >>= 1) {
        if (tid < o) red[tid] += red[tid + o];
        __syncthreads();
    }
    if (tid == 0) { g_mx[b] = mx; g_sz[b] = red[0]; }
}

__global__ void k_attn(const int* __restrict__ labels) {
    int i = blockIdx.x * 256 + threadIdx.x;
    int n = i >> 3, h = i & 7;
    int b = labels[n] * HNUM + h;
    g_attn[i] = expf(g_s[i] - g_mx[b]) / g_sz[b];
}

// ---------------- ws[c,h,e] = sum_{n in c} attn[n,h]*feat[n,e] ----------------
__global__ void k_wsump() {
    __shared__ float as[HNUM];
    int c = blockIdx.x, j = blockIdx.y, tid = threadIdx.x;
    int start = g_off[c], len = g_off[c + 1] - start;
    int ms = start + (len * j) / 8;
    int me = start + (len * (j + 1)) / 8;
    float acc[HNUM][2];
    #pragma unroll
    for (int h = 0; h < HNUM; h++) { acc[h][0] = 0.f; acc[h][1] = 0.f; }
    for (int m = ms; m < me; m++) {
        int idx = g_idx[m];
        if (tid < HNUM) as[tid] = g_attn[idx * HNUM + tid];
        __syncthreads();
        float2 f = *(const float2*)(g_feat + (size_t)idx * EDIM + 2 * tid);
        #pragma unroll
        for (int h = 0; h < HNUM; h++) {
            acc[h][0] += as[h] * f.x;
            acc[h][1] += as[h] * f.y;
        }
        __syncthreads();
    }
    #pragma unroll
    for (int h = 0; h < HNUM; h++) {
        size_t base = ((size_t)(c * 8 + j) * HNUM + h) * EDIM + 2 * tid;
        g_wsp[base]     = acc[h][0];
        g_wsp[base + 1] = acc[h][1];
    }
}

__global__ void k_wsred() {
    int b = blockIdx.x;        // c*8+h
    int c = b >> 3, h = b & 7, e = threadIdx.x;
    float s = 0.f;
    #pragma unroll
    for (int j = 0; j < 8; j++) s += g_wsp[((size_t)(c * 8 + j) * HNUM + h) * EDIM + e];
    g_ws[(size_t)b * EDIM + e] = s;
}

// ---------------- out[c,x] = ws[c, x/64, :] @ Wv[:, x] + bv[x] ----------------
__global__ void k_out(const float* __restrict__ Wv, const float* __restrict__ bv) {
    __shared__ float ws_s[HNUM * EDIM];
    int c = blockIdx.x, x = threadIdx.x;
    #pragma unroll
    for (int j = 0; j < 8; j++) ws_s[j * EDIM + x] = g_ws[(size_t)(c * HNUM) * EDIM + j * EDIM + x];
    __syncthreads();
    int h = x >> 6;
    float acc = 0.f;
    for (int e = 0; e < EDIM; e++) acc += ws_s[h * EDIM + e] * Wv[(size_t)e * EDIM + x];
    g_out[c * EDIM + x] = acc + bv[x];
}

// ---------------- proto = out@Wo + bo; final accumulate ----------------
__global__ void k_proto(const float* __restrict__ Wo, const float* __restrict__ bo,
                        int lvl, float* __restrict__ fin) {
    __shared__ float os[EDIM];
    int c = blockIdx.x, e = threadIdx.x;
    os[e] = g_out[c * EDIM + e];
    __syncthreads();
    float acc = 0.f;
    for (int k = 0; k < EDIM; k++) acc += os[k] * Wo[(size_t)k * EDIM + e];
    float v = (acc + bo[e]) * g_coef[lvl];
    if (lvl == 0) fin[c * EDIM + e] = v;
    else          fin[c * EDIM + e] += v;
}

// ---------------- launch ----------------
extern "C" void kernel_launch(void* const* d_in, const int* in_sizes, int n_in,
                              void* d_out, int out_size) {
    const float* X      = (const float*)d_in[0];
    const int*   labels = (const int*)d_in[1];
    const float* W1     = (const float*)d_in[2];
    const float* b1     = (const float*)d_in[3];
    const float* gamma  = (const float*)d_in[4];
    const float* beta   = (const float*)d_in[5];
    const float* W2     = (const float*)d_in[6];
    const float* b2     = (const float*)d_in[7];
    const float* Wq     = (const float*)d_in[8];
    const float* bq     = (const float*)d_in[9];
    const float* Wk     = (const float*)d_in[10];
    // d_in[11]=bk cancels in softmax
    const float* Wv     = (const float*)d_in[12];
    const float* bv     = (const float*)d_in[13];
    const float* Wo     = (const float*)d_in[14];
    const float* bo     = (const float*)d_in[15];
    const float* lw     = (const float*)d_in[16];
    const float* lt     = (const float*)d_in[17];
    float* fin = (float*)d_out;

    cudaFuncSetAttribute(k_gemm5, cudaFuncAttributeMaxDynamicSharedMemorySize, GEMM_SMEM);

    __half* pXh; cudaGetSymbolAddress((void**)&pXh, g_Xh);
    __half* ph;  cudaGetSymbolAddress((void**)&ph,  g_h);
    __half* pW1; cudaGetSymbolAddress((void**)&pW1, g_W1t);
    __half* pW2; cudaGetSymbolAddress((void**)&pW2, g_W2t);
    float*  pF;  cudaGetSymbolAddress((void**)&pF,  g_feat);

    k_prep<<<1, 64>>>(lw, lt);
    k_convX<<<(NSUP * EDIM / 8) / 256, 256>>>(X);
    k_transW<<<dim3(16, 16, 7), dim3(32, 32)>>>(W1, W2, Wk);
    k_hist<<<NSUP / 256, 256>>>(labels);
    k_scan<<<1, 32>>>();
    k_scatter<<<CNUM, 256>>>(labels);

    for (int l = 0; l < LNUM; l++) {
        k_gemm5<<<dim3(NSUP / TBM, EDIM / TBN), 256, GEMM_SMEM>>>(
            pXh, pW1 + (size_t)l * EDIM * EDIM, b1 + l * EDIM, pF);
        k_lnrelu<<<NSUP / 8, 256>>>(gamma + l * EDIM, beta + l * EDIM);
        k_gemm5<<<dim3(NSUP / TBM, EDIM / TBN), 256, GEMM_SMEM>>>(
            ph, pW2 + (size_t)l * EDIM * EDIM, b2 + l * EDIM, pF);
        k_ctxp<<<dim3(CNUM, 8), 256>>>();
        k_ctxred<<<CNUM, EDIM>>>();
        k_q<<<CNUM, EDIM>>>(Wq, bq);
        k_u<<<dim3(CNUM, HNUM), EDIM>>>();
        k_score<<<NSUP * HNUM / 256, 256>>>(labels);
        k_smax<<<CNUM * HNUM, 256>>>();
        k_attn<<<NSUP * HNUM / 256, 256>>>(labels);
        k_wsump<<<dim3(CNUM, 8), 256>>>();
        k_wsred<<<CNUM * HNUM, EDIM>>>();
        k_out<<<CNUM, EDIM>>>(Wv, bv);
        k_proto<<<CNUM, EDIM>>>(Wo, bo, l, fin);
    }
}